// round 1
// baseline (speedup 1.0000x reference)
#include <cuda_runtime.h>

#define BB 2
#define HH 8
#define SS 4096
#define DK 64
#define DM 512
#define BH (BB*HH)

// Scratch (static device globals — no runtime allocation)
__device__ float g_Q[BH*SS*DK];
__device__ float g_K[BH*SS*DK];
__device__ float g_V[BH*SS*DK];
__device__ float g_O[BB*SS*DM];

// ---------------- GEMM config: 128x128x8 tile, 256 threads, 8x8 micro ----------------
#define GBM 128
#define GBN 128
#define GBK 8
#define ASTRIDE 132   // padded (odd /4) -> aligned float4 reads, low STS conflicts
#define BSTRIDE 128

// Fused QKV projection: X[8192,512] @ {Wq,Wk,Wv} -> g_Q/g_K/g_V in [bh, s, dk] layout
__global__ __launch_bounds__(256) void qkv_kernel(const float* __restrict__ X,
                                                  const float* __restrict__ Wq,
                                                  const float* __restrict__ Wk,
                                                  const float* __restrict__ Wv)
{
    __shared__ float As[GBK*ASTRIDE];
    __shared__ float Bs[GBK*BSTRIDE];
    const int tid = threadIdx.x;
    const int nb  = blockIdx.x;      // 0..11  (12 * 128 = 1536 virtual N)
    const int mb  = blockIdx.y;      // 0..63
    const int proj = nb >> 2;        // 0=Q,1=K,2=V (512/128 = 4 tiles per proj)
    const float* W = (proj == 0) ? Wq : (proj == 1) ? Wk : Wv;
    float* OutBase = (proj == 0) ? g_Q : (proj == 1) ? g_K : g_V;
    const int cb = (nb & 3) * GBN;   // col offset within this proj's 512

    const int m0 = (tid >> 4) * 8;
    const int n0 = (tid & 15) * 8;

    float acc[8][8];
    #pragma unroll
    for (int i = 0; i < 8; i++)
        #pragma unroll
        for (int j = 0; j < 8; j++) acc[i][j] = 0.f;

    const int arow = tid >> 1;           // 0..127
    const int acol = (tid & 1) * 4;      // 0 or 4
    const int brow = tid >> 5;           // 0..7
    const int bcol = (tid & 31) * 4;     // 0..124

    const float* Aptr = X + (mb*GBM + arow)*DM + acol;
    const float* Bptr = W + brow*DM + cb + bcol;

    for (int k0 = 0; k0 < DM; k0 += GBK) {
        float4 va = *(const float4*)(Aptr + k0);
        float4 vb = *(const float4*)(Bptr + (size_t)k0*DM);
        As[(acol+0)*ASTRIDE + arow] = va.x;
        As[(acol+1)*ASTRIDE + arow] = va.y;
        As[(acol+2)*ASTRIDE + arow] = va.z;
        As[(acol+3)*ASTRIDE + arow] = va.w;
        *(float4*)(Bs + brow*BSTRIDE + bcol) = vb;
        __syncthreads();
        #pragma unroll
        for (int k = 0; k < GBK; k++) {
            float4 a0 = *(const float4*)(As + k*ASTRIDE + m0);
            float4 a1 = *(const float4*)(As + k*ASTRIDE + m0 + 4);
            float4 b0 = *(const float4*)(Bs + k*BSTRIDE + n0);
            float4 b1 = *(const float4*)(Bs + k*BSTRIDE + n0 + 4);
            float av[8] = {a0.x,a0.y,a0.z,a0.w,a1.x,a1.y,a1.z,a1.w};
            float bv[8] = {b0.x,b0.y,b0.z,b0.w,b1.x,b1.y,b1.z,b1.w};
            #pragma unroll
            for (int i = 0; i < 8; i++)
                #pragma unroll
                for (int j = 0; j < 8; j++)
                    acc[i][j] = fmaf(av[i], bv[j], acc[i][j]);
        }
        __syncthreads();
    }

    // epilogue: scatter into head-major layout [(b*H+h), s, d]
    #pragma unroll
    for (int i = 0; i < 8; i++) {
        int gm = mb*GBM + m0 + i;
        int b = gm >> 12, s = gm & (SS-1);
        #pragma unroll
        for (int j = 0; j < 8; j++) {
            int wc = cb + n0 + j;
            int h = wc >> 6, d = wc & 63;
            OutBase[(((size_t)(b*HH + h)*SS) + s)*DK + d] = acc[i][j];
        }
    }
}

// Output projection: g_O[8192,512] @ Wo -> d_out
__global__ __launch_bounds__(256) void oproj_kernel(const float* __restrict__ Wo,
                                                    float* __restrict__ Out)
{
    __shared__ float As[GBK*ASTRIDE];
    __shared__ float Bs[GBK*BSTRIDE];
    const int tid = threadIdx.x;
    const int nb  = blockIdx.x;      // 0..3
    const int mb  = blockIdx.y;      // 0..63
    const int cb = nb * GBN;

    const int m0 = (tid >> 4) * 8;
    const int n0 = (tid & 15) * 8;

    float acc[8][8];
    #pragma unroll
    for (int i = 0; i < 8; i++)
        #pragma unroll
        for (int j = 0; j < 8; j++) acc[i][j] = 0.f;

    const int arow = tid >> 1;
    const int acol = (tid & 1) * 4;
    const int brow = tid >> 5;
    const int bcol = (tid & 31) * 4;

    const float* Aptr = g_O + (size_t)(mb*GBM + arow)*DM + acol;
    const float* Bptr = Wo + brow*DM + cb + bcol;

    for (int k0 = 0; k0 < DM; k0 += GBK) {
        float4 va = *(const float4*)(Aptr + k0);
        float4 vb = *(const float4*)(Bptr + (size_t)k0*DM);
        As[(acol+0)*ASTRIDE + arow] = va.x;
        As[(acol+1)*ASTRIDE + arow] = va.y;
        As[(acol+2)*ASTRIDE + arow] = va.z;
        As[(acol+3)*ASTRIDE + arow] = va.w;
        *(float4*)(Bs + brow*BSTRIDE + bcol) = vb;
        __syncthreads();
        #pragma unroll
        for (int k = 0; k < GBK; k++) {
            float4 a0 = *(const float4*)(As + k*ASTRIDE + m0);
            float4 a1 = *(const float4*)(As + k*ASTRIDE + m0 + 4);
            float4 b0 = *(const float4*)(Bs + k*BSTRIDE + n0);
            float4 b1 = *(const float4*)(Bs + k*BSTRIDE + n0 + 4);
            float av[8] = {a0.x,a0.y,a0.z,a0.w,a1.x,a1.y,a1.z,a1.w};
            float bv[8] = {b0.x,b0.y,b0.z,b0.w,b1.x,b1.y,b1.z,b1.w};
            #pragma unroll
            for (int i = 0; i < 8; i++)
                #pragma unroll
                for (int j = 0; j < 8; j++)
                    acc[i][j] = fmaf(av[i], bv[j], acc[i][j]);
        }
        __syncthreads();
    }

    #pragma unroll
    for (int i = 0; i < 8; i++) {
        int gm = mb*GBM + m0 + i;
        #pragma unroll
        for (int j = 0; j < 8; j++)
            Out[(size_t)gm*DM + cb + n0 + j] = acc[i][j];
    }
}

// ---------------- Flash attention: 64 q-rows per CTA, 64-wide K/V tiles ----------------
#define AP 68   // padded smem stride (68*4 bytes, 16B-aligned float4 rows)

__global__ __launch_bounds__(256) void attn_kernel()
{
    extern __shared__ float sm[];
    float* Qs = sm;                 // Qs[d*AP + m]   (transposed)
    float* KP = sm + 64*AP;         // Ks[d*AP + n] during S-gemm; Ps[n*AP + m] during O-gemm
    float* Vs = sm + 2*64*AP;       // Vs[n*AP + d]   (natural)

    const int tid = threadIdx.x;
    const int tx = tid & 15, ty = tid >> 4;
    const int m0 = ty * 4, n0 = tx * 4;
    const int qt = blockIdx.x;      // 0..63 q tile
    const int bh = blockIdx.y;      // 0..15

    const float* Qg = g_Q + ((size_t)bh*SS + qt*64)*DK;
    const float* Kg = g_K + (size_t)bh*SS*DK;
    const float* Vg = g_V + (size_t)bh*SS*DK;

    // load Q tile transposed (once)
    #pragma unroll
    for (int r = 0; r < 4; r++) {
        int e = tid + r*256;
        int row = e >> 4;
        int c4  = (e & 15) * 4;
        float4 v = *(const float4*)(Qg + row*DK + c4);
        Qs[(c4+0)*AP + row] = v.x;
        Qs[(c4+1)*AP + row] = v.y;
        Qs[(c4+2)*AP + row] = v.z;
        Qs[(c4+3)*AP + row] = v.w;
    }

    float oacc[4][4];
    float mrow[4], lrow[4];
    #pragma unroll
    for (int i = 0; i < 4; i++) {
        mrow[i] = -1e30f; lrow[i] = 0.f;
        #pragma unroll
        for (int j = 0; j < 4; j++) oacc[i][j] = 0.f;
    }

    for (int kt = 0; kt < SS/64; kt++) {
        __syncthreads();   // previous iter readers done before overwrite (also covers Q stores)

        // load K transposed + V natural
        #pragma unroll
        for (int r = 0; r < 4; r++) {
            int e = tid + r*256;
            int row = e >> 4;
            int c4  = (e & 15) * 4;
            float4 kv = *(const float4*)(Kg + (size_t)(kt*64 + row)*DK + c4);
            KP[(c4+0)*AP + row] = kv.x;
            KP[(c4+1)*AP + row] = kv.y;
            KP[(c4+2)*AP + row] = kv.z;
            KP[(c4+3)*AP + row] = kv.w;
            float4 vv = *(const float4*)(Vg + (size_t)(kt*64 + row)*DK + c4);
            *(float4*)(Vs + row*AP + c4) = vv;
        }
        __syncthreads();

        // S = (Q K^T) * scale
        float s[4][4];
        #pragma unroll
        for (int i = 0; i < 4; i++)
            #pragma unroll
            for (int j = 0; j < 4; j++) s[i][j] = 0.f;

        #pragma unroll 8
        for (int d = 0; d < DK; d++) {
            float4 a = *(const float4*)(Qs + d*AP + m0);
            float4 b = *(const float4*)(KP + d*AP + n0);
            float av[4] = {a.x,a.y,a.z,a.w};
            float bv[4] = {b.x,b.y,b.z,b.w};
            #pragma unroll
            for (int i = 0; i < 4; i++)
                #pragma unroll
                for (int j = 0; j < 4; j++)
                    s[i][j] = fmaf(av[i], bv[j], s[i][j]);
        }
        #pragma unroll
        for (int i = 0; i < 4; i++)
            #pragma unroll
            for (int j = 0; j < 4; j++) s[i][j] *= 0.125f;

        // online softmax (rows live on 16-lane groups: same ty)
        float rmax[4], rsum[4], alpha[4];
        #pragma unroll
        for (int i = 0; i < 4; i++) {
            float mx = s[i][0];
            mx = fmaxf(mx, s[i][1]); mx = fmaxf(mx, s[i][2]); mx = fmaxf(mx, s[i][3]);
            #pragma unroll
            for (int o = 8; o > 0; o >>= 1)
                mx = fmaxf(mx, __shfl_xor_sync(0xffffffffu, mx, o, 16));
            rmax[i] = mx;
        }
        #pragma unroll
        for (int i = 0; i < 4; i++) {
            float mnew = fmaxf(mrow[i], rmax[i]);
            alpha[i] = __expf(mrow[i] - mnew);
            float rs = 0.f;
            #pragma unroll
            for (int j = 0; j < 4; j++) {
                s[i][j] = __expf(s[i][j] - mnew);
                rs += s[i][j];
            }
            #pragma unroll
            for (int o = 8; o > 0; o >>= 1)
                rs += __shfl_xor_sync(0xffffffffu, rs, o, 16);
            rsum[i] = rs;
            mrow[i] = mnew;
        }
        #pragma unroll
        for (int i = 0; i < 4; i++) {
            lrow[i] = lrow[i]*alpha[i] + rsum[i];
            #pragma unroll
            for (int j = 0; j < 4; j++) oacc[i][j] *= alpha[i];
        }

        __syncthreads();   // everyone finished reading KP (as K) before P overwrite
        // write P transposed: Ps[n][m]
        #pragma unroll
        for (int j = 0; j < 4; j++)
            #pragma unroll
            for (int i = 0; i < 4; i++)
                KP[(n0+j)*AP + (m0+i)] = s[i][j];
        __syncthreads();

        // O += P @ V  (inner dim = n)
        #pragma unroll 8
        for (int n = 0; n < 64; n++) {
            float4 a = *(const float4*)(KP + n*AP + m0);
            float4 b = *(const float4*)(Vs + n*AP + n0);  // out cols = n0..n0+3
            float av[4] = {a.x,a.y,a.z,a.w};
            float bv[4] = {b.x,b.y,b.z,b.w};
            #pragma unroll
            for (int i = 0; i < 4; i++)
                #pragma unroll
                for (int j = 0; j < 4; j++)
                    oacc[i][j] = fmaf(av[i], bv[j], oacc[i][j]);
        }
    }

    // finalize: O / l, write to concat layout [b, s, h*64 + d]
    const int b = bh >> 3, h = bh & 7;
    #pragma unroll
    for (int i = 0; i < 4; i++) {
        float inv = 1.f / lrow[i];
        int srow = qt*64 + m0 + i;
        #pragma unroll
        for (int j = 0; j < 4; j++)
            g_O[((size_t)(b*SS + srow))*DM + h*DK + n0 + j] = oacc[i][j] * inv;
    }
}

extern "C" void kernel_launch(void* const* d_in, const int* in_sizes, int n_in,
                              void* d_out, int out_size) {
    const float* x  = (const float*)d_in[0];
    const float* Wq = (const float*)d_in[1];
    const float* Wk = (const float*)d_in[2];
    const float* Wv = (const float*)d_in[3];
    const float* Wo = (const float*)d_in[4];
    float* out = (float*)d_out;

    (void)in_sizes; (void)n_in; (void)out_size;

    static const int ATTN_SMEM = 3 * 64 * AP * 4;  // 52224 bytes
    cudaFuncSetAttribute(attn_kernel, cudaFuncAttributeMaxDynamicSharedMemorySize, ATTN_SMEM);

    qkv_kernel<<<dim3(12, 64), 256>>>(x, Wq, Wk, Wv);
    attn_kernel<<<dim3(64, 16), 256, ATTN_SMEM>>>();
    oproj_kernel<<<dim3(4, 64), 256>>>(Wo, out);
}

// round 3
// speedup vs baseline: 3.1574x; 3.1574x over previous
#include <cuda_runtime.h>
#include <cstdint>

#define SS 4096
#define DK 64
#define DM 512
#define HH 8
#define BB 2
#define BH 16

// Scratch (static device globals — no runtime allocation)
__device__ float g_Q[BH*SS*DK];   // tf32-rounded, pre-scaled by 1/8
__device__ float g_K[BH*SS*DK];   // tf32-rounded
__device__ float g_V[BH*SS*DK];   // tf32-rounded
__device__ float g_O[BB*SS*DM];   // fp32 attention output (concat layout)

__device__ __forceinline__ uint32_t f2tf(float f) {
    uint32_t u; asm("cvt.rna.tf32.f32 %0, %1;" : "=r"(u) : "f"(f)); return u;
}

// D += A(16x8,row) * B(8x8,col), tf32 inputs, f32 accum
__device__ __forceinline__ void mma8(float* d, const uint32_t* a, const uint32_t* b) {
    asm volatile("mma.sync.aligned.m16n8k8.row.col.f32.tf32.tf32.f32 "
        "{%0,%1,%2,%3}, {%4,%5,%6,%7}, {%8,%9}, {%0,%1,%2,%3};"
        : "+f"(d[0]), "+f"(d[1]), "+f"(d[2]), "+f"(d[3])
        : "r"(a[0]), "r"(a[1]), "r"(a[2]), "r"(a[3]), "r"(b[0]), "r"(b[1]));
}

// ================= Projection GEMM: 128x128x16, 256 thr, warp tile 64x32 =================
#define PBM 128
#define PBN 128
#define PBK 16
#define AST 20    // As[m][k] stride -> frag loads conflict-free
#define BST 136   // Bs[k][n] stride -> frag loads conflict-free

// Fused QKV: X[8192,512] @ {Wq,Wk,Wv} -> g_Q/g_K/g_V head-major, tf32-rounded
__global__ __launch_bounds__(256) void qkv_kernel(const float* __restrict__ X,
                                                  const float* __restrict__ Wq,
                                                  const float* __restrict__ Wk,
                                                  const float* __restrict__ Wv)
{
    __shared__ uint32_t As[PBM*AST];
    __shared__ uint32_t Bs[PBK*BST];
    const int tid = threadIdx.x;
    const int nb = blockIdx.x, mb = blockIdx.y;   // nb 0..11 (3 proj x 4 tiles)
    const int proj = nb >> 2;
    const float* W = (proj==0) ? Wq : (proj==1) ? Wk : Wv;
    float* OutB   = (proj==0) ? g_Q : (proj==1) ? g_K : g_V;
    const int cb = (nb & 3) * PBN;

    const int warp = tid >> 5, lane = tid & 31;
    const int g = lane >> 2, c = lane & 3;
    const int wm = (warp & 1) * 64, wn = (warp >> 1) * 32;

    float acc[4][4][4];
    #pragma unroll
    for (int i=0;i<4;i++)
        #pragma unroll
        for (int j=0;j<4;j++)
            #pragma unroll
            for (int k=0;k<4;k++) acc[i][j][k] = 0.f;

    const int la_row = tid >> 1,  la_c = (tid & 1) * 8;
    const int lb_row = tid >> 4,  lb_c = (tid & 15) * 8;
    const float* Ap = X + (size_t)(mb*PBM + la_row)*DM + la_c;
    const float* Bp = W + (size_t)lb_row*DM + cb + lb_c;

    float4 ra0 = *(const float4*)(Ap);
    float4 ra1 = *(const float4*)(Ap + 4);
    float4 rb0 = *(const float4*)(Bp);
    float4 rb1 = *(const float4*)(Bp + 4);

    for (int k0 = 0; k0 < DM; k0 += PBK) {
        uint32_t* as = As + la_row*AST + la_c;
        as[0]=f2tf(ra0.x); as[1]=f2tf(ra0.y); as[2]=f2tf(ra0.z); as[3]=f2tf(ra0.w);
        as[4]=f2tf(ra1.x); as[5]=f2tf(ra1.y); as[6]=f2tf(ra1.z); as[7]=f2tf(ra1.w);
        uint32_t* bs = Bs + lb_row*BST + lb_c;
        bs[0]=f2tf(rb0.x); bs[1]=f2tf(rb0.y); bs[2]=f2tf(rb0.z); bs[3]=f2tf(rb0.w);
        bs[4]=f2tf(rb1.x); bs[5]=f2tf(rb1.y); bs[6]=f2tf(rb1.z); bs[7]=f2tf(rb1.w);
        __syncthreads();
        if (k0 + PBK < DM) {
            ra0 = *(const float4*)(Ap + k0 + PBK);
            ra1 = *(const float4*)(Ap + k0 + PBK + 4);
            rb0 = *(const float4*)(Bp + (size_t)(k0+PBK)*DM);
            rb1 = *(const float4*)(Bp + (size_t)(k0+PBK)*DM + 4);
        }
        #pragma unroll
        for (int ks = 0; ks < 2; ks++) {
            uint32_t a[4][4];
            #pragma unroll
            for (int mi=0; mi<4; mi++) {
                const uint32_t* ap = As + (wm + mi*16 + g)*AST + ks*8 + c;
                a[mi][0] = ap[0];
                a[mi][1] = ap[8*AST];
                a[mi][2] = ap[4];
                a[mi][3] = ap[8*AST + 4];
            }
            #pragma unroll
            for (int ni=0; ni<4; ni++) {
                uint32_t b[2];
                const uint32_t* bp = Bs + (ks*8 + c)*BST + wn + ni*8 + g;
                b[0] = bp[0];
                b[1] = bp[4*BST];
                #pragma unroll
                for (int mi=0; mi<4; mi++) mma8(acc[mi][ni], a[mi], b);
            }
        }
        __syncthreads();
    }

    const float qscale = (proj == 0) ? 0.125f : 1.0f;
    #pragma unroll
    for (int mi=0; mi<4; mi++) {
        #pragma unroll
        for (int h=0; h<2; h++) {
            int gm = mb*PBM + wm + mi*16 + g + h*8;
            int b = gm >> 12, s = gm & (SS-1);
            #pragma unroll
            for (int ni=0; ni<4; ni++) {
                int wc = cb + wn + ni*8 + 2*c;
                int hd = wc >> 6, d = wc & 63;
                float v0 = acc[mi][ni][h*2+0]*qscale;
                float v1 = acc[mi][ni][h*2+1]*qscale;
                float* o = OutB + (((size_t)(b*HH + hd)*SS) + s)*DK + d;
                o[0] = __uint_as_float(f2tf(v0));
                o[1] = __uint_as_float(f2tf(v1));
            }
        }
    }
}

// Output projection: g_O[8192,512] @ Wo -> d_out (fp32 out)
__global__ __launch_bounds__(256) void oproj_kernel(const float* __restrict__ Wo,
                                                    float* __restrict__ Out)
{
    __shared__ uint32_t As[PBM*AST];
    __shared__ uint32_t Bs[PBK*BST];
    const int tid = threadIdx.x;
    const int nb = blockIdx.x, mb = blockIdx.y;
    const int cb = nb * PBN;

    const int warp = tid >> 5, lane = tid & 31;
    const int g = lane >> 2, c = lane & 3;
    const int wm = (warp & 1) * 64, wn = (warp >> 1) * 32;

    float acc[4][4][4];
    #pragma unroll
    for (int i=0;i<4;i++)
        #pragma unroll
        for (int j=0;j<4;j++)
            #pragma unroll
            for (int k=0;k<4;k++) acc[i][j][k] = 0.f;

    const int la_row = tid >> 1,  la_c = (tid & 1) * 8;
    const int lb_row = tid >> 4,  lb_c = (tid & 15) * 8;
    const float* Ap = g_O + (size_t)(mb*PBM + la_row)*DM + la_c;
    const float* Bp = Wo + (size_t)lb_row*DM + cb + lb_c;

    float4 ra0 = *(const float4*)(Ap);
    float4 ra1 = *(const float4*)(Ap + 4);
    float4 rb0 = *(const float4*)(Bp);
    float4 rb1 = *(const float4*)(Bp + 4);

    for (int k0 = 0; k0 < DM; k0 += PBK) {
        uint32_t* as = As + la_row*AST + la_c;
        as[0]=f2tf(ra0.x); as[1]=f2tf(ra0.y); as[2]=f2tf(ra0.z); as[3]=f2tf(ra0.w);
        as[4]=f2tf(ra1.x); as[5]=f2tf(ra1.y); as[6]=f2tf(ra1.z); as[7]=f2tf(ra1.w);
        uint32_t* bs = Bs + lb_row*BST + lb_c;
        bs[0]=f2tf(rb0.x); bs[1]=f2tf(rb0.y); bs[2]=f2tf(rb0.z); bs[3]=f2tf(rb0.w);
        bs[4]=f2tf(rb1.x); bs[5]=f2tf(rb1.y); bs[6]=f2tf(rb1.z); bs[7]=f2tf(rb1.w);
        __syncthreads();
        if (k0 + PBK < DM) {
            ra0 = *(const float4*)(Ap + k0 + PBK);
            ra1 = *(const float4*)(Ap + k0 + PBK + 4);
            rb0 = *(const float4*)(Bp + (size_t)(k0+PBK)*DM);
            rb1 = *(const float4*)(Bp + (size_t)(k0+PBK)*DM + 4);
        }
        #pragma unroll
        for (int ks = 0; ks < 2; ks++) {
            uint32_t a[4][4];
            #pragma unroll
            for (int mi=0; mi<4; mi++) {
                const uint32_t* ap = As + (wm + mi*16 + g)*AST + ks*8 + c;
                a[mi][0] = ap[0];
                a[mi][1] = ap[8*AST];
                a[mi][2] = ap[4];
                a[mi][3] = ap[8*AST + 4];
            }
            #pragma unroll
            for (int ni=0; ni<4; ni++) {
                uint32_t b[2];
                const uint32_t* bp = Bs + (ks*8 + c)*BST + wn + ni*8 + g;
                b[0] = bp[0];
                b[1] = bp[4*BST];
                #pragma unroll
                for (int mi=0; mi<4; mi++) mma8(acc[mi][ni], a[mi], b);
            }
        }
        __syncthreads();
    }

    #pragma unroll
    for (int mi=0; mi<4; mi++) {
        #pragma unroll
        for (int h=0; h<2; h++) {
            int gm = mb*PBM + wm + mi*16 + g + h*8;
            #pragma unroll
            for (int ni=0; ni<4; ni++) {
                float2 v = { acc[mi][ni][h*2+0], acc[mi][ni][h*2+1] };
                *(float2*)(Out + (size_t)gm*DM + cb + wn + ni*8 + 2*c) = v;
            }
        }
    }
}

// ================= Flash attention (tf32 tensor cores) =================
// CTA: 128 threads (4 warps), 128 q-rows (warp: 32), K/V tile 64
#define QST 68
#define KST 68
#define VST 68
#define PST 68   // P tile per warp is 32 x 64 (k = key dim), padded stride
#define SMW_K (128*QST)
#define SMW_V (SMW_K + 64*KST)
#define SMW_P (SMW_V + 64*VST)
#define SMW_TOTAL (SMW_P + 4*32*PST)   // 26112 words = 104448 bytes

__global__ __launch_bounds__(128) void attn_kernel()
{
    extern __shared__ uint32_t smu[];
    uint32_t* Qs = smu;
    uint32_t* Ks = smu + SMW_K;
    uint32_t* Vs = smu + SMW_V;

    const int tid = threadIdx.x;
    const int warp = tid >> 5, lane = tid & 31;
    const int g = lane >> 2, c = lane & 3;
    uint32_t* Ps = smu + SMW_P + warp*32*PST;

    const int qt = blockIdx.x;   // 0..31
    const int bh = blockIdx.y;   // 0..15

    const uint32_t* Qg = (const uint32_t*)g_Q + ((size_t)bh*SS + qt*128)*DK;
    const uint32_t* Kg = (const uint32_t*)g_K + (size_t)bh*SS*DK;
    const uint32_t* Vg = (const uint32_t*)g_V + (size_t)bh*SS*DK;

    // Load Q tile (128x64), already tf32-rounded + pre-scaled
    #pragma unroll
    for (int i = 0; i < 16; i++) {
        int e = tid + i*128;
        int row = e >> 4, c4 = (e & 15) * 4;
        *(uint4*)(Qs + row*QST + c4) = *(const uint4*)(Qg + row*DK + c4);
    }

    float o[2][8][4];
    float mr[2][2], lr[2][2];
    #pragma unroll
    for (int mi=0;mi<2;mi++) {
        mr[mi][0]=mr[mi][1]=-1e30f; lr[mi][0]=lr[mi][1]=0.f;
        #pragma unroll
        for (int n=0;n<8;n++)
            #pragma unroll
            for (int k=0;k<4;k++) o[mi][n][k]=0.f;
    }

    for (int kt = 0; kt < SS/64; kt++) {
        __syncthreads();
        #pragma unroll
        for (int i = 0; i < 8; i++) {
            int e = tid + i*128;
            int row = e >> 4, c4 = (e & 15) * 4;
            *(uint4*)(Ks + row*KST + c4) = *(const uint4*)(Kg + (size_t)(kt*64+row)*DK + c4);
            *(uint4*)(Vs + row*VST + c4) = *(const uint4*)(Vg + (size_t)(kt*64+row)*DK + c4);
        }
        __syncthreads();

        // S = Q K^T (Q pre-scaled by 1/8)
        float s[2][8][4];
        #pragma unroll
        for (int mi=0;mi<2;mi++)
            #pragma unroll
            for (int n=0;n<8;n++)
                #pragma unroll
                for (int k=0;k<4;k++) s[mi][n][k]=0.f;

        #pragma unroll
        for (int kf = 0; kf < 8; kf++) {
            uint32_t a[2][4];
            #pragma unroll
            for (int mi=0;mi<2;mi++) {
                const uint32_t* qp = Qs + (warp*32 + mi*16 + g)*QST + kf*8 + c;
                a[mi][0]=qp[0]; a[mi][1]=qp[8*QST]; a[mi][2]=qp[4]; a[mi][3]=qp[8*QST+4];
            }
            #pragma unroll
            for (int n=0;n<8;n++) {
                uint32_t b[2];
                const uint32_t* kp = Ks + (n*8 + g)*KST + kf*8 + c;
                b[0]=kp[0]; b[1]=kp[4];
                mma8(s[0][n], a[0], b);
                mma8(s[1][n], a[1], b);
            }
        }

        // Online softmax
        #pragma unroll
        for (int mi=0;mi<2;mi++) {
            #pragma unroll
            for (int h=0;h<2;h++) {
                float mx = -1e30f;
                #pragma unroll
                for (int n=0;n<8;n++) mx = fmaxf(mx, fmaxf(s[mi][n][h*2], s[mi][n][h*2+1]));
                mx = fmaxf(mx, __shfl_xor_sync(0xffffffffu, mx, 1));
                mx = fmaxf(mx, __shfl_xor_sync(0xffffffffu, mx, 2));
                float mnew = fmaxf(mr[mi][h], mx);
                float alpha = __expf(mr[mi][h] - mnew);
                mr[mi][h] = mnew;
                float rs = 0.f;
                #pragma unroll
                for (int n=0;n<8;n++) {
                    float p0 = __expf(s[mi][n][h*2]   - mnew);
                    float p1 = __expf(s[mi][n][h*2+1] - mnew);
                    s[mi][n][h*2] = p0; s[mi][n][h*2+1] = p1;
                    rs += p0 + p1;
                }
                rs += __shfl_xor_sync(0xffffffffu, rs, 1);
                rs += __shfl_xor_sync(0xffffffffu, rs, 2);
                lr[mi][h] = lr[mi][h]*alpha + rs;
                #pragma unroll
                for (int n=0;n<8;n++) { o[mi][n][h*2] *= alpha; o[mi][n][h*2+1] *= alpha; }
            }
        }

        // P -> per-warp smem (tf32), then reload as A fragments
        #pragma unroll
        for (int mi=0;mi<2;mi++)
            #pragma unroll
            for (int n=0;n<8;n++) {
                uint2 v0; v0.x = f2tf(s[mi][n][0]); v0.y = f2tf(s[mi][n][1]);
                *(uint2*)(Ps + (mi*16 + g    )*PST + n*8 + 2*c) = v0;
                uint2 v1; v1.x = f2tf(s[mi][n][2]); v1.y = f2tf(s[mi][n][3]);
                *(uint2*)(Ps + (mi*16 + g + 8)*PST + n*8 + 2*c) = v1;
            }
        __syncwarp();

        // O += P V
        #pragma unroll
        for (int kf=0; kf<8; kf++) {
            uint32_t a[2][4];
            #pragma unroll
            for (int mi=0;mi<2;mi++) {
                const uint32_t* pp = Ps + (mi*16 + g)*PST + kf*8 + c;
                a[mi][0]=pp[0]; a[mi][1]=pp[8*PST]; a[mi][2]=pp[4]; a[mi][3]=pp[8*PST+4];
            }
            #pragma unroll
            for (int n=0;n<8;n++) {
                uint32_t b[2];
                const uint32_t* vp = Vs + (kf*8 + c)*VST + n*8 + g;
                b[0]=vp[0]; b[1]=vp[4*VST];
                mma8(o[0][n], a[0], b);
                mma8(o[1][n], a[1], b);
            }
        }
    }

    // Finalize, write concat layout [b][s][h*64+d]
    const int b = bh >> 3, hd = bh & 7;
    #pragma unroll
    for (int mi=0;mi<2;mi++)
        #pragma unroll
        for (int h=0;h<2;h++) {
            float inv = 1.f / lr[mi][h];
            int row = qt*128 + warp*32 + mi*16 + g + h*8;
            float* op = g_O + ((size_t)(b*SS + row))*DM + hd*DK;
            #pragma unroll
            for (int n=0;n<8;n++) {
                float2 v = { o[mi][n][h*2]*inv, o[mi][n][h*2+1]*inv };
                *(float2*)(op + n*8 + 2*c) = v;
            }
        }
}

extern "C" void kernel_launch(void* const* d_in, const int* in_sizes, int n_in,
                              void* d_out, int out_size) {
    const float* x  = (const float*)d_in[0];
    const float* Wq = (const float*)d_in[1];
    const float* Wk = (const float*)d_in[2];
    const float* Wv = (const float*)d_in[3];
    const float* Wo = (const float*)d_in[4];
    float* out = (float*)d_out;
    (void)in_sizes; (void)n_in; (void)out_size;

    static const int ATTN_SMEM = SMW_TOTAL * 4;  // 104448 bytes
    cudaFuncSetAttribute(attn_kernel, cudaFuncAttributeMaxDynamicSharedMemorySize, ATTN_SMEM);

    qkv_kernel<<<dim3(12, 64), 256>>>(x, Wq, Wk, Wv);
    attn_kernel<<<dim3(32, 16), 128, ATTN_SMEM>>>();
    oproj_kernel<<<dim3(4, 64), 256>>>(Wo, out);
}